// round 11
// baseline (speedup 1.0000x reference)
#include <cuda_runtime.h>
#include <cuda_bf16.h>

// Problem constants (B=8, R=C=1024, EXTENTS=(-40,40)^2)
#define BN 8
#define RN 1024
#define CN 1024
#define RC (RN * CN)
#define GS 0.078125f        // 80/1024, exactly representable
#define PIX_TH 0.05f
#define GB 2                // batches per group (32MB slice, L2 resident)
#define NGROUPS (BN / GB)   // 4

// ---------------------------------------------------------------------------
// Zero the first group's slice (plain head kernel).
// ---------------------------------------------------------------------------
__global__ void rtree_zero_kernel(float4* __restrict__ out) {
    int i = blockIdx.x * blockDim.x + threadIdx.x;
    out[i] = make_float4(0.f, 0.f, 0.f, 0.f);
}

// ---------------------------------------------------------------------------
// Scatter for group g (PDL consumer), which ALSO zeros slice g+1 pre-sync.
// Pre-sync phase (overlaps predecessor): input loads, target computation,
// and zero-stores to the NEXT group's slice (disjoint from everything the
// predecessor touches). Post-sync: atomics into slice g (zeroed by the
// previous scatter / head kernel). One red.v4 per fg pixel = op-optimal.
// ---------------------------------------------------------------------------
__global__ void __launch_bounds__(256)
rtree_scatter_kernel(const float* __restrict__ pixel,
                     const float* __restrict__ conf,
                     const float* __restrict__ off,
                     const float* __restrict__ vel,
                     float* __restrict__ out,
                     int b0, int do_zero) {
    const int b = b0 + blockIdx.y;
    const int t = blockIdx.x * blockDim.x + threadIdx.x;  // 0 .. RC/4-1
    const int r = t >> 8;
    const int c = (t & 255) << 2;

    // ---- pre-sync: zero next group's slice (coalesced, 4 float4/thread) ----
    // Linear thread id across the whole grid: gridDim = (1024, GB), 256 thr.
    const int lt = ((blockIdx.y * gridDim.x + blockIdx.x) * 256) + threadIdx.x;
    const int nthreads = gridDim.x * gridDim.y * 256;      // 524288
    if (do_zero) {
        float4* zer = ((float4*)out) + (long)(b0 + GB) * RC;
        const float4 z = make_float4(0.f, 0.f, 0.f, 0.f);
#pragma unroll
        for (int k = 0; k < GB * RC / 4; k += 1) {         // GB*RC cells tot
            // GB*RC cells / nthreads = 4 iterations
            if (k == 4) break;
            zer[lt + k * nthreads] = z;
        }
    }

    // ---- pre-sync: input loads + target computation ----
    const long base  = (long)b * RC + (long)r * CN + c;
    const long base2 = (long)b * 2 * RC + (long)r * CN + c;

    const float4 p    = __ldcs((const float4*)(pixel + base));
    const float4 cf   = __ldcs((const float4*)(conf  + base));
    const float4 orow = __ldcs((const float4*)(off + base2));
    const float4 ocol = __ldcs((const float4*)(off + base2 + RC));
    const float4 vx   = __ldcs((const float4*)(vel + base2));
    const float4 vy   = __ldcs((const float4*)(vel + base2 + RC));

    float* const outb = out + (long)b * RC * 4;

    const float* pp  = &p.x;
    const float* pc  = &cf.x;
    const float* por = &orow.x;
    const float* poc = &ocol.x;
    const float* pvx = &vx.x;
    const float* pvy = &vy.x;

    float vals[4][4];
    float* addrs[4];
#pragma unroll
    for (int j = 0; j < 4; j++) {
        addrs[j] = nullptr;
        if (pp[j] > PIX_TH) {
            // Exact IEEE div (matches XLA div.rn.f32) + round-half-even
            int sr = __float2int_rn(__fdiv_rn(por[j], GS));
            int sc = __float2int_rn(__fdiv_rn(poc[j], GS));
            int tr = min(max(r + sr, 0), RN - 1);
            int tc = min(max(c + j + sc, 0), CN - 1);
            addrs[j] = outb + (((long)(tr << 10) + tc) << 2);
            vals[j][0] = 1.0f; vals[j][1] = pc[j];
            vals[j][2] = pvx[j]; vals[j][3] = pvy[j];
        }
    }

    // Wait for predecessor (fin(g-1) trigger => scatter(g-1) completed =>
    // this group's zeros are visible), then fire atomics.
    cudaGridDependencySynchronize();

#pragma unroll
    for (int j = 0; j < 4; j++) {
        if (addrs[j]) {
            asm volatile(
                "red.global.add.v4.f32 [%0], {%1, %2, %3, %4};"
                :: "l"(addrs[j]), "f"(vals[j][0]), "f"(vals[j][1]),
                   "f"(vals[j][2]), "f"(vals[j][3])
                : "memory");
        }
    }
}

// ---------------------------------------------------------------------------
// Finalize slice g (pure PDL consumer). Triggers IMMEDIATELY after its
// grid-sync: the next scatter depends on nothing fin writes (disjoint
// slices; its zeros were produced by scatter(g)). The finalize work then
// overlaps the next scatter's execution.
// ---------------------------------------------------------------------------
__global__ void rtree_fin_kernel(float4* __restrict__ fin) {
    cudaGridDependencySynchronize();          // wait scatter(g) complete
    cudaTriggerProgrammaticLaunchCompletion(); // unblock scatter(g+1) now

    int i = blockIdx.x * blockDim.x + threadIdx.x;
    float4 v = __ldcs(&fin[i]);
    if (!(v.x > 0.0f)) {
        __stcs(&fin[i], make_float4(-0.1f, -0.1f, -0.1f, -0.1f));
    }
}

// ---------------------------------------------------------------------------
// PDL launch helper.
// ---------------------------------------------------------------------------
template <typename F, typename... Args>
static inline void launch_pdl(F f, dim3 grid, dim3 block, Args... args) {
    cudaLaunchConfig_t cfg = {};
    cfg.gridDim = grid;
    cfg.blockDim = block;
    cfg.dynamicSmemBytes = 0;
    cfg.stream = 0;
    cudaLaunchAttribute attr[1];
    attr[0].id = cudaLaunchAttributeProgrammaticStreamSerialization;
    attr[0].val.programmaticStreamSerializationAllowed = 1;
    cfg.attrs = attr;
    cfg.numAttrs = 1;
    cudaLaunchKernelEx(&cfg, f, args...);
}

// ---------------------------------------------------------------------------
// Launch: 4 groups of 2 batches; zeros embedded in scatters' pre-sync phase;
// fins trigger early so only scatters + tails sit on the critical path.
//   chain: zero0 | scat0(+zero1) | fin0 | scat1(+zero2) | fin1 | ... | fin3
// Inputs (metadata order):
//   [0] voxel_count_gt int32 (B,R,C)   -- randint(0,5) >= 0 always, unused
//   [1] pixel_pred     f32   (B,R,C)
//   [2] confidence_pred f32  (B,R,C)
//   [3] offset_pred    f32   (B,2,R,C)
//   [4] view_index     int32 (B,R,C,5) -- unused
//   [5] velocity_pred  f32   (B,2,R,C)
// Output: f32 (B,R,C,4)
// ---------------------------------------------------------------------------
extern "C" void kernel_launch(void* const* d_in, const int* in_sizes, int n_in,
                              void* d_out, int out_size) {
    const float* pixel = (const float*)d_in[1];
    const float* conf  = (const float*)d_in[2];
    const float* off   = (const float*)d_in[3];
    const float* vel   = (const float*)d_in[5];
    float* out = (float*)d_out;

    const int gcells  = GB * RC;            // float4 cells per group
    const int gblocks = gcells / 256;
    dim3 sgrid(RC / 4 / 256, GB);           // (1024, GB)

    rtree_zero_kernel<<<gblocks, 256>>>((float4*)out);

    for (int g = 0; g < NGROUPS; g++) {
        float4* gcur = ((float4*)out) + (long)g * gcells;
        int do_zero = (g + 1 < NGROUPS) ? 1 : 0;

        launch_pdl(rtree_scatter_kernel, sgrid, dim3(256),
                   pixel, conf, off, vel, out, g * GB, do_zero);
        launch_pdl(rtree_fin_kernel, dim3(gblocks), dim3(256), gcur);
    }
}